// round 16
// baseline (speedup 1.0000x reference)
#include <cuda_runtime.h>
#include <cuda_bf16.h>
#include <cstdint>

#define NUM_ENT 40000
#define ED      256
#define FD      768
#define BATCH   32
#define NE_OUT  (NUM_ENT + 1)
#define ET_LD   40128

typedef unsigned long long u64;

// g_Et stores NEGATED values. Column map:
//   col c in [0,40000) : -ent_proj[c] (unity row c+1)
//   col 40000+r        : -other_emb[r] (unity rows 0, 40001..40102)
__device__ float          g_Et[ED * ET_LD];
__device__ __nv_bfloat16  g_Bb[FD * ED];
__device__ float          g_qsum[ED * BATCH];
__device__ int            g_qcol[BATCH * 2];

// ---------------- helpers ----------------
__device__ __forceinline__ u64 addf32x2(u64 a, u64 b) {
    u64 r;
    asm("add.rn.f32x2 %0, %1, %2;" : "=l"(r) : "l"(a), "l"(b));
    return r;
}
__device__ __forceinline__ u64 pack2(float x) {
    u64 r;
    asm("mov.b64 %0, {%1,%1};" : "=l"(r) : "f"(x));
    return r;
}
__device__ __forceinline__ void ldsm4(uint32_t r[4], uint32_t addr) {
    asm volatile("ldmatrix.sync.aligned.m8n8.x4.shared.b16 {%0,%1,%2,%3}, [%4];"
                 : "=r"(r[0]), "=r"(r[1]), "=r"(r[2]), "=r"(r[3])
                 : "r"(addr));
}
__device__ __forceinline__ void mma16816(float c[4], const uint32_t a[4],
                                         uint32_t b0, uint32_t b1) {
    asm volatile(
        "mma.sync.aligned.m16n8k16.row.col.f32.bf16.bf16.f32 "
        "{%0,%1,%2,%3}, {%4,%5,%6,%7}, {%8,%9}, {%0,%1,%2,%3};"
        : "+f"(c[0]), "+f"(c[1]), "+f"(c[2]), "+f"(c[3])
        : "r"(a[0]), "r"(a[1]), "r"(a[2]), "r"(a[3]), "r"(b0), "r"(b1));
}
__device__ __forceinline__ uint32_t smaddr(const void* p) {
    return (uint32_t)__cvta_generic_to_shared(p);
}

// ---------------- prep: convB + fill edges + decode ids (ONE kernel) ---------
__global__ void prep_kernel(const float* __restrict__ W,
                            const float* __restrict__ other,
                            const void* __restrict__ ids_raw,
                            const int* __restrict__ mp_ptr) {
    int i = blockIdx.x * 256 + threadIdx.x;
    if (i < FD * ED) g_Bb[i] = __float2bfloat16(W[i]);
    if (i < 103 * ED) {
        int r = i / ED, d = i % ED;
        g_Et[d * ET_LD + NUM_ENT + r] = -other[i];
    }
    if (blockIdx.x == 0 && threadIdx.x == 0) {
        const int* p = (const int*)ids_raw;
        bool is64 = true;
        for (int k = 1; k < BATCH * 3; k += 2)
            if (p[k] != 0) { is64 = false; break; }
        int mp = 2;
        if (mp_ptr) {
            int im = *mp_ptr;
            if (im >= 0 && im < 3) mp = im;
            else {
                float f = __int_as_float(im);
                if (f >= 0.f && f < 3.f) mp = (int)f;
            }
        }
        for (int b = 0; b < BATCH; b++)
            for (int j = 0; j < 2; j++) {
                int col3 = (j < mp) ? j : j + 1;
                int idx  = b * 3 + col3;
                int id   = is64 ? (int)((const long long*)ids_raw)[idx] : p[idx];
                int col  = (id == 0) ? NUM_ENT : (id <= NUM_ENT ? id - 1 : id);
                g_qcol[b * 2 + j] = col;
            }
    }
}

// ---------------- GEMM tile (templated N width) ----------------
// BM=128, BK=64, 512 threads (4m x 4n warps), 4-stage smem ring,
// 2 chunks per barrier interval (6 barriers in mainloop).
#define BM       128
#define BK       64
#define ASTRIDE  72
#define A_ST     (BM * ASTRIDE)                 // 9216 bf16
#define B_ST_F   (256 * ASTRIDE)                // 18432 bf16
#define STG_F    (A_ST + B_ST_F)
#define GEMM_SMEM (4 * STG_F * 2)               // 221184 B

#define N_FULL_TILES 296                        // 2 exact waves of 148
#define N_TAIL_TILES 17                         // m-tiles 296..312
#define GRID_GEMM    (N_FULL_TILES + 2 * N_TAIL_TILES)   // 330

template <int BNR>
__device__ __forceinline__ void gemm_tile(const float* __restrict__ A,
                                          int bm0, int n0,
                                          __nv_bfloat16* sm) {
    constexpr int B_ST  = BNR * ASTRIDE;
    constexpr int STG   = A_ST + B_ST;
    constexpr int NBH   = (BNR * 8 / 512) / 2;   // B uint4-slots per half
    constexpr int NWARP = BNR / 4;
    constexpr int NT    = NWARP / 8;
    constexpr int NF2   = NWARP / 16;

    const int tid  = threadIdx.x;
    const int lane = tid & 31;
    const int warp = tid >> 5;
    const int wm   = warp >> 2;
    const int wn   = warp & 3;

    float acc[2][NT][4];
#pragma unroll
    for (int i = 0; i < 2; i++)
#pragma unroll
        for (int j = 0; j < NT; j++)
#pragma unroll
            for (int k = 0; k < 4; k++) acc[i][j][k] = 0.f;

    float4 va[2];
    uint4  vb[2];

    auto sA = [&](int s) { return sm + s * STG; };
    auto sB = [&](int s) { return sm + s * STG + A_ST; };

    auto loadHalfA = [&](int kc, int h) {
#pragma unroll
        for (int i = 0; i < 2; i++) {
            int s = tid + 512 * (2 * h + i);
            int r = s >> 4, sl = s & 15;
            if (bm0 + r < NUM_ENT)
                va[i] = *(const float4*)(A + (size_t)(bm0 + r) * FD + kc + sl * 4);
            else
                va[i] = make_float4(0.f, 0.f, 0.f, 0.f);
        }
    };
    auto stsHalfA = [&](int st, int h) {
#pragma unroll
        for (int i = 0; i < 2; i++) {
            int s = tid + 512 * (2 * h + i);
            int r = s >> 4, sl = s & 15;
            __nv_bfloat162 p0 = __floats2bfloat162_rn(va[i].x, va[i].y);
            __nv_bfloat162 p1 = __floats2bfloat162_rn(va[i].z, va[i].w);
            uint32_t u0 = *(uint32_t*)&p0, u1 = *(uint32_t*)&p1;
            uint32_t ad = smaddr(&sA(st)[r * ASTRIDE + sl * 4]);
            asm volatile("st.shared.v2.b32 [%0], {%1,%2};"
                         :: "r"(ad), "r"(u0), "r"(u1) : "memory");
        }
    };
    auto loadHalfB = [&](int kc, int h) {
#pragma unroll
        for (int i = 0; i < NBH; i++) {
            int s = tid + 512 * (NBH * h + i);
            int r = s >> 3, q = s & 7;
            vb[i] = *(const uint4*)((const __nv_bfloat16*)g_Bb +
                                    (size_t)(n0 + r) * FD + kc + q * 8);
        }
    };
    auto stsHalfB = [&](int st, int h) {
#pragma unroll
        for (int i = 0; i < NBH; i++) {
            int s = tid + 512 * (NBH * h + i);
            int r = s >> 3, q = s & 7;
            *(uint4*)&sB(st)[r * ASTRIDE + q * 8] = vb[i];
        }
    };

    const int quad = lane >> 3, l8 = lane & 7;
    const int arow_l = (quad & 1) * 8 + l8;
    const int acol_q = (quad >> 1) * 8;
    const int brow_l = (quad >> 1) * 8 + l8;
    const int bcol_q = (quad & 1) * 8;

    auto mmaSub = [&](int st, int ks) {
        const int k0 = ks * 16;
        uint32_t a[2][4], b[NF2][4];
#pragma unroll
        for (int mf = 0; mf < 2; mf++) {
            uint32_t ad = smaddr(&sA(st)[(wm * 32 + mf * 16 + arow_l) * ASTRIDE +
                                         k0 + acol_q]);
            ldsm4(a[mf], ad);
        }
#pragma unroll
        for (int nf2 = 0; nf2 < NF2; nf2++) {
            uint32_t ad = smaddr(&sB(st)[(wn * NWARP + nf2 * 16 + brow_l) * ASTRIDE +
                                         k0 + bcol_q]);
            ldsm4(b[nf2], ad);
        }
#pragma unroll
        for (int mf = 0; mf < 2; mf++)
#pragma unroll
            for (int nt = 0; nt < NT; nt++)
                mma16816(acc[mf][nt], a[mf],
                         b[nt >> 1][(nt & 1) * 2],
                         b[nt >> 1][(nt & 1) * 2 + 1]);
    };

    // prologue: chunks 0,1 -> stages 0,1
    loadHalfA(0, 0);  loadHalfB(0, 0);  stsHalfA(0, 0); stsHalfB(0, 0);
    loadHalfA(0, 1);  loadHalfB(0, 1);  stsHalfA(0, 1); stsHalfB(0, 1);
    loadHalfA(BK, 0); loadHalfB(BK, 0); stsHalfA(1, 0); stsHalfB(1, 0);
    loadHalfA(BK, 1); loadHalfB(BK, 1); stsHalfA(1, 1); stsHalfB(1, 1);

    // mainloop: 6 intervals, 2 chunks each; 4-stage ring (stage = chunk & 3)
#pragma unroll 1
    for (int i = 0; i < (FD / BK) / 2; i++) {
        __syncthreads();                 // chunks 2i,2i+1 visible; stages (2i+2)&3,(2i+3)&3 free
        const int s0  = (2 * i) & 3;
        const int s1  = s0 + 1;
        const int ns0 = s0 ^ 2;
        const int ns1 = ns0 + 1;
        const int kc2 = (2 * i + 2) * BK;
        const int kc3 = (2 * i + 3) * BK;
        const bool more = (2 * i + 2 < FD / BK);
        if (more) { loadHalfA(kc2, 0); loadHalfB(kc2, 0); }
        mmaSub(s0, 0);
        mmaSub(s0, 1);
        if (more) {
            stsHalfA(ns0, 0); stsHalfB(ns0, 0);
            loadHalfA(kc2, 1); loadHalfB(kc2, 1);
        }
        mmaSub(s0, 2);
        mmaSub(s0, 3);
        if (more) {
            stsHalfA(ns0, 1); stsHalfB(ns0, 1);
            loadHalfA(kc3, 0); loadHalfB(kc3, 0);
        }
        mmaSub(s1, 0);
        mmaSub(s1, 1);
        if (more) {
            stsHalfA(ns1, 0); stsHalfB(ns1, 0);
            loadHalfA(kc3, 1); loadHalfB(kc3, 1);
        }
        mmaSub(s1, 2);
        mmaSub(s1, 3);
        if (more) { stsHalfA(ns1, 1); stsHalfB(ns1, 1); }
    }
    __syncthreads();

    // epilogue (negated stores)
    float* s_out = (float*)sm;
    const int g = lane >> 2, tg = lane & 3;
    if constexpr (BNR == 256) {
#pragma unroll
        for (int pair = 0; pair < 2; pair++) {
            if ((wn >> 1) == pair) {
                float* buf = s_out + (wn & 1) * (64 * 132);
#pragma unroll
                for (int mf = 0; mf < 2; mf++)
#pragma unroll
                    for (int nt = 0; nt < NT; nt++) {
                        int srow = nt * 8 + tg * 2;
                        int scol = wm * 32 + mf * 16 + g;
                        buf[srow * 132 + scol]           = -acc[mf][nt][0];
                        buf[(srow + 1) * 132 + scol]     = -acc[mf][nt][1];
                        buf[srow * 132 + scol + 8]       = -acc[mf][nt][2];
                        buf[(srow + 1) * 132 + scol + 8] = -acc[mf][nt][3];
                    }
            }
            __syncthreads();
#pragma unroll
            for (int i = 0; i < 8; i++) {
                int idx = tid + i * 512;
                int buf = idx >> 11;
                int n   = (idx >> 5) & 63;
                int m4  = idx & 31;
                if (bm0 + m4 * 4 + 4 <= NUM_ENT) {
                    float4 v = *(float4*)&s_out[buf * (64 * 132) + n * 132 + m4 * 4];
                    int nrow = (pair * 2 + buf) * 64 + n;
                    *(float4*)&g_Et[(size_t)nrow * ET_LD + bm0 + m4 * 4] = v;
                }
            }
            __syncthreads();
        }
    } else {
        {
            float* buf = s_out + (wn >> 1) * (64 * 132);
#pragma unroll
            for (int mf = 0; mf < 2; mf++)
#pragma unroll
                for (int nt = 0; nt < NT; nt++) {
                    int srow = (wn & 1) * 32 + nt * 8 + tg * 2;
                    int scol = wm * 32 + mf * 16 + g;
                    buf[srow * 132 + scol]           = -acc[mf][nt][0];
                    buf[(srow + 1) * 132 + scol]     = -acc[mf][nt][1];
                    buf[srow * 132 + scol + 8]       = -acc[mf][nt][2];
                    buf[(srow + 1) * 132 + scol + 8] = -acc[mf][nt][3];
                }
        }
        __syncthreads();
#pragma unroll
        for (int i = 0; i < 8; i++) {
            int idx = tid + i * 512;
            int buf = idx >> 11;
            int n   = (idx >> 5) & 63;
            int m4  = idx & 31;
            if (bm0 + m4 * 4 + 4 <= NUM_ENT) {
                float4 v = *(float4*)&s_out[buf * (64 * 132) + n * 132 + m4 * 4];
                int nrow = n0 + buf * 64 + n;
                *(float4*)&g_Et[(size_t)nrow * ET_LD + bm0 + m4 * 4] = v;
            }
        }
        __syncthreads();
    }
}

__global__ void __launch_bounds__(512, 1) gemm_bf16_kernel(const float* __restrict__ A) {
    extern __shared__ __nv_bfloat16 sm[];
    const int bx = blockIdx.x;
    if (bx < N_FULL_TILES) {
        gemm_tile<256>(A, bx * BM, 0, sm);
    } else {
        int t = bx - N_FULL_TILES;
        int mt = N_FULL_TILES + (t >> 1);
        gemm_tile<128>(A, mt * BM, (t & 1) * 128, sm);
    }
}

// ---------------- query_sum ----------------
__global__ void __launch_bounds__(256) qsum_kernel() {
    __shared__ float s_red[2][8];
    const int b = blockIdx.x, tid = threadIdx.x;
    const int c0 = g_qcol[b * 2], c1 = g_qcol[b * 2 + 1];

    const int d = tid;
    float v0 = g_Et[d * ET_LD + c0];
    float v1 = g_Et[d * ET_LD + c1];
    float ss0 = v0 * v0, ss1 = v1 * v1;
#pragma unroll
    for (int o = 16; o > 0; o >>= 1) {
        ss0 += __shfl_xor_sync(0xffffffffu, ss0, o);
        ss1 += __shfl_xor_sync(0xffffffffu, ss1, o);
    }
    if ((tid & 31) == 0) { s_red[0][tid >> 5] = ss0; s_red[1][tid >> 5] = ss1; }
    __syncthreads();
    ss0 = 0.f; ss1 = 0.f;
#pragma unroll
    for (int w = 0; w < 8; w++) { ss0 += s_red[0][w]; ss1 += s_red[1][w]; }
    float r0 = -1.0f / fmaxf(sqrtf(ss0), 1e-12f);
    float r1 = -1.0f / fmaxf(sqrtf(ss1), 1e-12f);
    g_qsum[d * BATCH + b] = v0 * r0 + v1 * r1;
}

// ---------------- score: 1 col/thread, prefetch distance 8 ----------------
__global__ void __launch_bounds__(256) score_kernel(float* __restrict__ out) {
    __shared__ u64 sq[ED][4];
    const int tid = threadIdx.x;
    const int by  = blockIdx.y;

    {
        float4* dst = (float4*)&sq[0][0];
#pragma unroll
        for (int i = 0; i < 2; i++) {
            int idx = tid + i * 256;
            int d = idx >> 1, h = idx & 1;
            dst[d * 2 + h] = *(const float4*)(g_qsum + d * BATCH + by * 8 + h * 4);
        }
    }
    __syncthreads();

    const int c = blockIdx.x * 256 + tid;
    const bool active = (c <= NUM_ENT);
    const float* ecol = g_Et + (active ? c : 0);

    u64 acc[4];
#pragma unroll
    for (int i = 0; i < 4; i++) acc[i] = 0ULL;

    float cur[4], mid[4], nxt[4];
#pragma unroll
    for (int j = 0; j < 4; j++) cur[j] = ecol[j * ET_LD];
#pragma unroll
    for (int j = 0; j < 4; j++) mid[j] = ecol[(4 + j) * ET_LD];

    const u64 MSK = 0x7FFFFFFF7FFFFFFFULL;
    auto body = [&](int d0, const float cv[4]) {
        u64 q[4][4];
#pragma unroll
        for (int j = 0; j < 4; j++) {
            ulonglong2 t0 = *(const ulonglong2*)&sq[d0 + j][0];
            ulonglong2 t1 = *(const ulonglong2*)&sq[d0 + j][2];
            q[j][0] = t0.x; q[j][1] = t0.y; q[j][2] = t1.x; q[j][3] = t1.y;
        }
#pragma unroll
        for (int j = 0; j < 4; j++) {
            u64 e = pack2(cv[j]);
#pragma unroll
            for (int bp = 0; bp < 4; bp++)
                acc[bp] = addf32x2(acc[bp], addf32x2(q[j][bp], e) & MSK);
        }
    };

    for (int d0 = 0; d0 < ED - 8; d0 += 4) {
#pragma unroll
        for (int j = 0; j < 4; j++) nxt[j] = ecol[(d0 + 8 + j) * ET_LD];
        body(d0, cur);
#pragma unroll
        for (int j = 0; j < 4; j++) { cur[j] = mid[j]; mid[j] = nxt[j]; }
    }
    body(ED - 8, cur);
    body(ED - 4, mid);

    if (active) {
        int e = (c == NUM_ENT) ? 0 : c + 1;
#pragma unroll
        for (int bp = 0; bp < 4; bp++) {
            u64 a = acc[bp];
            float lo = __int_as_float((int)(a & 0xffffffffULL));
            float hi = __int_as_float((int)(a >> 32));
            int b = 8 * by + 2 * bp;
            out[(size_t)b * NE_OUT + e]       = -lo;
            out[(size_t)(b + 1) * NE_OUT + e] = -hi;
        }
    }
}

// ---------------- launcher ----------------
extern "C" void kernel_launch(void* const* d_in, const int* in_sizes, int n_in,
                              void* d_out, int out_size) {
    const float* ent   = (const float*)d_in[0];
    const float* other = (const float*)d_in[1];
    const float* W     = (const float*)d_in[2];
    const void*  ids   = d_in[3];
    const int*   mp    = (n_in > 4) ? (const int*)d_in[4] : nullptr;

    cudaFuncSetAttribute(gemm_bf16_kernel,
                         cudaFuncAttributeMaxDynamicSharedMemorySize, GEMM_SMEM);

    prep_kernel<<<(FD * ED + 255) / 256, 256>>>(W, other, ids, mp);
    gemm_bf16_kernel<<<GRID_GEMM, 512, GEMM_SMEM>>>(ent);
    qsum_kernel<<<BATCH, 256>>>();
    dim3 sg((NE_OUT + 255) / 256, 4);          // 157 x 4
    score_kernel<<<sg, 256>>>((float*)d_out);
}

// round 17
// speedup vs baseline: 1.0487x; 1.0487x over previous
#include <cuda_runtime.h>
#include <cuda_bf16.h>
#include <cstdint>

#define NUM_ENT 40000
#define ED      256
#define FD      768
#define BATCH   32
#define NE_OUT  (NUM_ENT + 1)
#define ET_LD   40128

typedef unsigned long long u64;

// g_Et stores NEGATED values. Column map:
//   col c in [0,40000) : -ent_proj[c] (unity row c+1)
//   col 40000+r        : -other_emb[r] (unity rows 0, 40001..40102)
__device__ float          g_Et[ED * ET_LD];
__device__ __nv_bfloat16  g_Bb[FD * ED];
__device__ float          g_qsum[ED * BATCH];
__device__ int            g_qcol[BATCH * 2];

// ---------------- helpers ----------------
__device__ __forceinline__ u64 addf32x2(u64 a, u64 b) {
    u64 r;
    asm("add.rn.f32x2 %0, %1, %2;" : "=l"(r) : "l"(a), "l"(b));
    return r;
}
__device__ __forceinline__ u64 pack2(float x) {
    u64 r;
    asm("mov.b64 %0, {%1,%1};" : "=l"(r) : "f"(x));
    return r;
}
__device__ __forceinline__ void ldsm4(uint32_t r[4], uint32_t addr) {
    asm volatile("ldmatrix.sync.aligned.m8n8.x4.shared.b16 {%0,%1,%2,%3}, [%4];"
                 : "=r"(r[0]), "=r"(r[1]), "=r"(r[2]), "=r"(r[3])
                 : "r"(addr));
}
__device__ __forceinline__ void mma16816(float c[4], const uint32_t a[4],
                                         uint32_t b0, uint32_t b1) {
    asm volatile(
        "mma.sync.aligned.m16n8k16.row.col.f32.bf16.bf16.f32 "
        "{%0,%1,%2,%3}, {%4,%5,%6,%7}, {%8,%9}, {%0,%1,%2,%3};"
        : "+f"(c[0]), "+f"(c[1]), "+f"(c[2]), "+f"(c[3])
        : "r"(a[0]), "r"(a[1]), "r"(a[2]), "r"(a[3]), "r"(b0), "r"(b1));
}
__device__ __forceinline__ uint32_t smaddr(const void* p) {
    return (uint32_t)__cvta_generic_to_shared(p);
}

// ---------------- prep: convB + fill edges + decode ids (ONE kernel) ---------
__global__ void prep_kernel(const float* __restrict__ W,
                            const float* __restrict__ other,
                            const void* __restrict__ ids_raw,
                            const int* __restrict__ mp_ptr) {
    int i = blockIdx.x * 256 + threadIdx.x;
    if (i < FD * ED) g_Bb[i] = __float2bfloat16(W[i]);
    if (i < 103 * ED) {
        int r = i / ED, d = i % ED;
        g_Et[d * ET_LD + NUM_ENT + r] = -other[i];
    }
    if (blockIdx.x == 0 && threadIdx.x == 0) {
        const int* p = (const int*)ids_raw;
        bool is64 = true;
        for (int k = 1; k < BATCH * 3; k += 2)
            if (p[k] != 0) { is64 = false; break; }
        int mp = 2;
        if (mp_ptr) {
            int im = *mp_ptr;
            if (im >= 0 && im < 3) mp = im;
            else {
                float f = __int_as_float(im);
                if (f >= 0.f && f < 3.f) mp = (int)f;
            }
        }
        for (int b = 0; b < BATCH; b++)
            for (int j = 0; j < 2; j++) {
                int col3 = (j < mp) ? j : j + 1;
                int idx  = b * 3 + col3;
                int id   = is64 ? (int)((const long long*)ids_raw)[idx] : p[idx];
                int col  = (id == 0) ? NUM_ENT : (id <= NUM_ENT ? id - 1 : id);
                g_qcol[b * 2 + j] = col;
            }
    }
}

// ---------------- GEMM tile (templated N width) — R13 skeleton --------------
// BM=128, BK=64, 512 threads (4m x 4n warps), 3-stage smem, LDG+STS loads.
// BNR=256: full tile. BNR=64: quarter tile at n offset n0 (tail CTAs).
#define BM       128
#define BK       64
#define ASTRIDE  72
#define A_ST     (BM * ASTRIDE)                 // 9216 bf16
#define B_ST_F   (256 * ASTRIDE)                // 18432 bf16
#define STG_F    (A_ST + B_ST_F)
#define GEMM_SMEM (3 * STG_F * 2)               // 165888 B

#define N_FULL_TILES 296                        // 2 exact waves of 148
#define N_TAIL_TILES 17                         // m-tiles 296..312
#define GRID_GEMM    (N_FULL_TILES + 4 * N_TAIL_TILES)   // 364

template <int BNR>
__device__ __forceinline__ void gemm_tile(const float* __restrict__ A,
                                          int bm0, int n0,
                                          __nv_bfloat16* sm) {
    constexpr int B_ST  = BNR * ASTRIDE;
    constexpr int STG   = A_ST + B_ST;
    constexpr int TB    = BNR * 8 / 512;         // B uint4-slots per thread: 4 or 1
    constexpr int HB    = (TB + 1) / 2;          // slots per half (ceil)
    constexpr int NWARP = BNR / 4;               // 64 or 16
    constexpr int NT    = NWARP / 8;             // 8 or 2
    constexpr int NF2   = NWARP / 16;            // 4 or 1

    const int tid  = threadIdx.x;
    const int lane = tid & 31;
    const int warp = tid >> 5;
    const int wm   = warp >> 2;
    const int wn   = warp & 3;

    float acc[2][NT][4];
#pragma unroll
    for (int i = 0; i < 2; i++)
#pragma unroll
        for (int j = 0; j < NT; j++)
#pragma unroll
            for (int k = 0; k < 4; k++) acc[i][j][k] = 0.f;

    float4 va[2];
    uint4  vb[HB];

    auto sA = [&](int s) { return sm + s * STG; };
    auto sB = [&](int s) { return sm + s * STG + A_ST; };

    auto loadHalfA = [&](int kc, int h) {
#pragma unroll
        for (int i = 0; i < 2; i++) {
            int s = tid + 512 * (2 * h + i);
            int r = s >> 4, sl = s & 15;
            if (bm0 + r < NUM_ENT)
                va[i] = *(const float4*)(A + (size_t)(bm0 + r) * FD + kc + sl * 4);
            else
                va[i] = make_float4(0.f, 0.f, 0.f, 0.f);
        }
    };
    auto stsHalfA = [&](int st, int h) {
#pragma unroll
        for (int i = 0; i < 2; i++) {
            int s = tid + 512 * (2 * h + i);
            int r = s >> 4, sl = s & 15;
            __nv_bfloat162 p0 = __floats2bfloat162_rn(va[i].x, va[i].y);
            __nv_bfloat162 p1 = __floats2bfloat162_rn(va[i].z, va[i].w);
            uint32_t u0 = *(uint32_t*)&p0, u1 = *(uint32_t*)&p1;
            uint32_t ad = smaddr(&sA(st)[r * ASTRIDE + sl * 4]);
            asm volatile("st.shared.v2.b32 [%0], {%1,%2};"
                         :: "r"(ad), "r"(u0), "r"(u1) : "memory");
        }
    };
    // B half-loaders: half h covers slots [h*HB, min(TB,(h+1)*HB))
    auto loadHalfB = [&](int kc, int h) {
#pragma unroll
        for (int i = 0; i < HB; i++) {
            int sl = h * HB + i;
            if (sl < TB) {
                int s = tid + 512 * sl;
                int r = s >> 3, q = s & 7;
                vb[i] = *(const uint4*)((const __nv_bfloat16*)g_Bb +
                                        (size_t)(n0 + r) * FD + kc + q * 8);
            }
        }
    };
    auto stsHalfB = [&](int st, int h) {
#pragma unroll
        for (int i = 0; i < HB; i++) {
            int sl = h * HB + i;
            if (sl < TB) {
                int s = tid + 512 * sl;
                int r = s >> 3, q = s & 7;
                *(uint4*)&sB(st)[r * ASTRIDE + q * 8] = vb[i];
            }
        }
    };

    const int quad = lane >> 3, l8 = lane & 7;
    const int arow_l = (quad & 1) * 8 + l8;
    const int acol_q = (quad >> 1) * 8;
    const int brow_l = (quad >> 1) * 8 + l8;
    const int bcol_q = (quad & 1) * 8;

    auto mmaSub = [&](int st, int ks) {
        const int k0 = ks * 16;
        uint32_t a[2][4], b[NF2][4];
#pragma unroll
        for (int mf = 0; mf < 2; mf++) {
            uint32_t ad = smaddr(&sA(st)[(wm * 32 + mf * 16 + arow_l) * ASTRIDE +
                                         k0 + acol_q]);
            ldsm4(a[mf], ad);
        }
#pragma unroll
        for (int nf2 = 0; nf2 < NF2; nf2++) {
            uint32_t ad = smaddr(&sB(st)[(wn * NWARP + nf2 * 16 + brow_l) * ASTRIDE +
                                         k0 + bcol_q]);
            ldsm4(b[nf2], ad);
        }
#pragma unroll
        for (int mf = 0; mf < 2; mf++)
#pragma unroll
            for (int nt = 0; nt < NT; nt++)
                mma16816(acc[mf][nt], a[mf],
                         b[nt >> 1][(nt & 1) * 2],
                         b[nt >> 1][(nt & 1) * 2 + 1]);
    };

    const int NC = FD / BK;    // 12
    loadHalfA(0, 0);  loadHalfB(0, 0);  stsHalfA(0, 0); stsHalfB(0, 0);
    loadHalfA(0, 1);  loadHalfB(0, 1);  stsHalfA(0, 1); stsHalfB(0, 1);
    loadHalfA(BK, 0); loadHalfB(BK, 0); stsHalfA(1, 0); stsHalfB(1, 0);
    loadHalfA(BK, 1); loadHalfB(BK, 1); stsHalfA(1, 1); stsHalfB(1, 1);

#pragma unroll 1
    for (int c = 0; c < NC; c++) {
        __syncthreads();
        const int st = c % 3;
        const int ns = (c + 2) % 3;
        const int kc2 = (c + 2) * BK;
        const bool more = (c + 2 < NC);
        if (more) { loadHalfA(kc2, 0); loadHalfB(kc2, 0); }
        mmaSub(st, 0);
        mmaSub(st, 1);
        if (more) {
            stsHalfA(ns, 0); stsHalfB(ns, 0);
            loadHalfA(kc2, 1); loadHalfB(kc2, 1);
        }
        mmaSub(st, 2);
        mmaSub(st, 3);
        if (more) { stsHalfA(ns, 1); stsHalfB(ns, 1); }
    }
    __syncthreads();

    // epilogue (negated stores)
    float* s_out = (float*)sm;
    const int g = lane >> 2, tg = lane & 3;
    if constexpr (BNR == 256) {
#pragma unroll
        for (int pair = 0; pair < 2; pair++) {
            if ((wn >> 1) == pair) {
                float* buf = s_out + (wn & 1) * (64 * 132);
#pragma unroll
                for (int mf = 0; mf < 2; mf++)
#pragma unroll
                    for (int nt = 0; nt < NT; nt++) {
                        int srow = nt * 8 + tg * 2;
                        int scol = wm * 32 + mf * 16 + g;
                        buf[srow * 132 + scol]           = -acc[mf][nt][0];
                        buf[(srow + 1) * 132 + scol]     = -acc[mf][nt][1];
                        buf[srow * 132 + scol + 8]       = -acc[mf][nt][2];
                        buf[(srow + 1) * 132 + scol + 8] = -acc[mf][nt][3];
                    }
            }
            __syncthreads();
#pragma unroll
            for (int i = 0; i < 8; i++) {
                int idx = tid + i * 512;
                int buf = idx >> 11;
                int n   = (idx >> 5) & 63;
                int m4  = idx & 31;
                if (bm0 + m4 * 4 + 4 <= NUM_ENT) {
                    float4 v = *(float4*)&s_out[buf * (64 * 132) + n * 132 + m4 * 4];
                    int nrow = (pair * 2 + buf) * 64 + n;
                    *(float4*)&g_Et[(size_t)nrow * ET_LD + bm0 + m4 * 4] = v;
                }
            }
            __syncthreads();
        }
    } else {
        // BNR=64: single buffer [64][132]; warp covers 16 n-rows
        {
#pragma unroll
            for (int mf = 0; mf < 2; mf++)
#pragma unroll
                for (int nt = 0; nt < NT; nt++) {
                    int srow = wn * 16 + nt * 8 + tg * 2;
                    int scol = wm * 32 + mf * 16 + g;
                    s_out[srow * 132 + scol]           = -acc[mf][nt][0];
                    s_out[(srow + 1) * 132 + scol]     = -acc[mf][nt][1];
                    s_out[srow * 132 + scol + 8]       = -acc[mf][nt][2];
                    s_out[(srow + 1) * 132 + scol + 8] = -acc[mf][nt][3];
                }
        }
        __syncthreads();
#pragma unroll
        for (int i = 0; i < 4; i++) {
            int idx = tid + i * 512;           // 0..2047
            int n   = idx >> 5;                // 0..63
            int m4  = idx & 31;
            if (bm0 + m4 * 4 + 4 <= NUM_ENT) {
                float4 v = *(float4*)&s_out[n * 132 + m4 * 4];
                int nrow = n0 + n;
                *(float4*)&g_Et[(size_t)nrow * ET_LD + bm0 + m4 * 4] = v;
            }
        }
        __syncthreads();
    }
}

__global__ void __launch_bounds__(512, 1) gemm_bf16_kernel(const float* __restrict__ A) {
    extern __shared__ __nv_bfloat16 sm[];
    const int bx = blockIdx.x;
    if (bx < N_FULL_TILES) {
        gemm_tile<256>(A, bx * BM, 0, sm);
    } else {
        int t = bx - N_FULL_TILES;            // 0..67
        int mt = N_FULL_TILES + (t >> 2);
        gemm_tile<64>(A, mt * BM, (t & 3) * 64, sm);
    }
}

// ---------------- query_sum ----------------
__global__ void __launch_bounds__(256) qsum_kernel() {
    __shared__ float s_red[2][8];
    const int b = blockIdx.x, tid = threadIdx.x;
    const int c0 = g_qcol[b * 2], c1 = g_qcol[b * 2 + 1];

    const int d = tid;
    float v0 = g_Et[d * ET_LD + c0];
    float v1 = g_Et[d * ET_LD + c1];
    float ss0 = v0 * v0, ss1 = v1 * v1;
#pragma unroll
    for (int o = 16; o > 0; o >>= 1) {
        ss0 += __shfl_xor_sync(0xffffffffu, ss0, o);
        ss1 += __shfl_xor_sync(0xffffffffu, ss1, o);
    }
    if ((tid & 31) == 0) { s_red[0][tid >> 5] = ss0; s_red[1][tid >> 5] = ss1; }
    __syncthreads();
    ss0 = 0.f; ss1 = 0.f;
#pragma unroll
    for (int w = 0; w < 8; w++) { ss0 += s_red[0][w]; ss1 += s_red[1][w]; }
    float r0 = -1.0f / fmaxf(sqrtf(ss0), 1e-12f);
    float r1 = -1.0f / fmaxf(sqrtf(ss1), 1e-12f);
    g_qsum[d * BATCH + b] = v0 * r0 + v1 * r1;
}

// ---------------- score: 1 col/thread, prefetch distance 8 ----------------
__global__ void __launch_bounds__(256) score_kernel(float* __restrict__ out) {
    __shared__ u64 sq[ED][4];
    const int tid = threadIdx.x;
    const int by  = blockIdx.y;

    {
        float4* dst = (float4*)&sq[0][0];
#pragma unroll
        for (int i = 0; i < 2; i++) {
            int idx = tid + i * 256;
            int d = idx >> 1, h = idx & 1;
            dst[d * 2 + h] = *(const float4*)(g_qsum + d * BATCH + by * 8 + h * 4);
        }
    }
    __syncthreads();

    const int c = blockIdx.x * 256 + tid;
    const bool active = (c <= NUM_ENT);
    const float* ecol = g_Et + (active ? c : 0);

    u64 acc[4];
#pragma unroll
    for (int i = 0; i < 4; i++) acc[i] = 0ULL;

    float cur[4], mid[4], nxt[4];
#pragma unroll
    for (int j = 0; j < 4; j++) cur[j] = ecol[j * ET_LD];
#pragma unroll
    for (int j = 0; j < 4; j++) mid[j] = ecol[(4 + j) * ET_LD];

    const u64 MSK = 0x7FFFFFFF7FFFFFFFULL;
    auto body = [&](int d0, const float cv[4]) {
        u64 q[4][4];
#pragma unroll
        for (int j = 0; j < 4; j++) {
            ulonglong2 t0 = *(const ulonglong2*)&sq[d0 + j][0];
            ulonglong2 t1 = *(const ulonglong2*)&sq[d0 + j][2];
            q[j][0] = t0.x; q[j][1] = t0.y; q[j][2] = t1.x; q[j][3] = t1.y;
        }
#pragma unroll
        for (int j = 0; j < 4; j++) {
            u64 e = pack2(cv[j]);
#pragma unroll
            for (int bp = 0; bp < 4; bp++)
                acc[bp] = addf32x2(acc[bp], addf32x2(q[j][bp], e) & MSK);
        }
    };

    for (int d0 = 0; d0 < ED - 8; d0 += 4) {
#pragma unroll
        for (int j = 0; j < 4; j++) nxt[j] = ecol[(d0 + 8 + j) * ET_LD];
        body(d0, cur);
#pragma unroll
        for (int j = 0; j < 4; j++) { cur[j] = mid[j]; mid[j] = nxt[j]; }
    }
    body(ED - 8, cur);
    body(ED - 4, mid);

    if (active) {
        int e = (c == NUM_ENT) ? 0 : c + 1;
#pragma unroll
        for (int bp = 0; bp < 4; bp++) {
            u64 a = acc[bp];
            float lo = __int_as_float((int)(a & 0xffffffffULL));
            float hi = __int_as_float((int)(a >> 32));
            int b = 8 * by + 2 * bp;
            out[(size_t)b * NE_OUT + e]       = -lo;
            out[(size_t)(b + 1) * NE_OUT + e] = -hi;
        }
    }
}

// ---------------- launcher ----------------
extern "C" void kernel_launch(void* const* d_in, const int* in_sizes, int n_in,
                              void* d_out, int out_size) {
    const float* ent   = (const float*)d_in[0];
    const float* other = (const float*)d_in[1];
    const float* W     = (const float*)d_in[2];
    const void*  ids   = d_in[3];
    const int*   mp    = (n_in > 4) ? (const int*)d_in[4] : nullptr;

    cudaFuncSetAttribute(gemm_bf16_kernel,
                         cudaFuncAttributeMaxDynamicSharedMemorySize, GEMM_SMEM);

    prep_kernel<<<(FD * ED + 255) / 256, 256>>>(W, other, ids, mp);
    gemm_bf16_kernel<<<GRID_GEMM, 512, GEMM_SMEM>>>(ent);
    qsum_kernel<<<BATCH, 256>>>();
    dim3 sg((NE_OUT + 255) / 256, 4);          // 157 x 4
    score_kernel<<<sg, 256>>>((float*)d_out);
}